// round 14
// baseline (speedup 1.0000x reference)
#include <cuda_runtime.h>
#include <cuda_bf16.h>
#include <cuda_fp16.h>
#include <cstdint>

#define SEQ   4096
#define HID   2048
#define NQKVZ 12288
#define CONVD 8192
#define KEYDIM 2048
#define VALDIM 4096

typedef unsigned long long ull;

// ------------ scratch ------------
__device__ float g_qkvz [(size_t)SEQ * NQKVZ];
__device__ float g_ba   [SEQ * 64];
__device__ float g_mixed[(size_t)SEQ * CONVD];
__device__ float g_qn   [(size_t)SEQ * KEYDIM];
__device__ float g_kn   [(size_t)SEQ * KEYDIM];
__device__ float g_eg   [SEQ * 32];
__device__ float g_beta [SEQ * 32];
__device__ float g_core [(size_t)SEQ * VALDIM];

__device__ __half g_Hh [(size_t)SEQ * HID];
__device__ __half g_Hl [(size_t)SEQ * HID];
__device__ __half g_W1 [(size_t)NQKVZ * HID];
__device__ __half g_Gh [(size_t)SEQ * VALDIM];
__device__ __half g_Gl [(size_t)SEQ * VALDIM];
__device__ __half g_W2 [(size_t)HID * VALDIM];

// ------------ f32x2 helpers ------------
__device__ __forceinline__ ull pk2(float a, float b){ ull r; asm("mov.b64 %0,{%1,%2};":"=l"(r):"f"(a),"f"(b)); return r; }
__device__ __forceinline__ void upk2(ull v, float& a, float& b){ asm("mov.b64 {%0,%1},%2;":"=f"(a),"=f"(b):"l"(v)); }
__device__ __forceinline__ ull fma2(ull a, ull b, ull c){ ull d; asm("fma.rn.f32x2 %0,%1,%2,%3;":"=l"(d):"l"(a),"l"(b),"l"(c)); return d; }
__device__ __forceinline__ ull mul2(ull a, ull b){ ull d; asm("mul.rn.f32x2 %0,%1,%2;":"=l"(d):"l"(a),"l"(b)); return d; }
__device__ __forceinline__ ull add2(ull a, ull b){ ull d; asm("add.rn.f32x2 %0,%1,%2;":"=l"(d):"l"(a),"l"(b)); return d; }

__device__ __forceinline__ void mma_f16(float* c, const unsigned* a, const unsigned* b){
    asm volatile("mma.sync.aligned.m16n8k16.row.col.f32.f16.f16.f32 "
        "{%0,%1,%2,%3},{%4,%5,%6,%7},{%8,%9},{%0,%1,%2,%3};\n"
        : "+f"(c[0]),"+f"(c[1]),"+f"(c[2]),"+f"(c[3])
        : "r"(a[0]),"r"(a[1]),"r"(a[2]),"r"(a[3]),"r"(b[0]),"r"(b[1]));
}
__device__ __forceinline__ void cp16(uint32_t dst, const void* src){
    asm volatile("cp.async.cg.shared.global [%0], [%1], 16;" :: "r"(dst), "l"(src));
}
__device__ __forceinline__ void cp4(uint32_t dst, const void* src){
    asm volatile("cp.async.ca.shared.global [%0], [%1], 4;" :: "r"(dst), "l"(src));
}
__device__ __forceinline__ void ldsm4(unsigned* r, uint32_t a){
    asm volatile("ldmatrix.sync.aligned.m8n8.x4.shared.b16 {%0,%1,%2,%3},[%4];"
        : "=r"(r[0]),"=r"(r[1]),"=r"(r[2]),"=r"(r[3]) : "r"(a));
}
__device__ __forceinline__ void ldsm2(unsigned* r, uint32_t a){
    asm volatile("ldmatrix.sync.aligned.m8n8.x2.shared.b16 {%0,%1},[%2];"
        : "=r"(r[0]),"=r"(r[1]) : "r"(a));
}

// ------------ 3-stage pipelined split-fp16 GEMM (unchanged from R13) ------------
#define STG_BYTES 24576
#define NSTG 3
__global__ __launch_bounds__(256, 2) void gemm_sp(const __half* __restrict__ Ah,
                                                  const __half* __restrict__ Al,
                                                  const __half* __restrict__ B,
                                                  float* __restrict__ C,
                                                  int M, int N, int K) {
    extern __shared__ char smem[];
    uint32_t sbase = (uint32_t)__cvta_generic_to_shared(smem);
    const int tid = threadIdx.x;
    const int bm = blockIdx.x*128, bn = blockIdx.y*128;
    const int warp = tid >> 5, lane = tid & 31;
    const int wm = (warp >> 2)*64, wn = (warp & 3)*32;

    float acc[4][4][4];
    #pragma unroll
    for (int i=0;i<4;i++)
      #pragma unroll
      for (int j=0;j<4;j++)
        #pragma unroll
        for (int k=0;k<4;k++) acc[i][j][k]=0.f;

    auto load_stage = [&](int c){
        uint32_t so = sbase + (c % NSTG)*STG_BYTES;
        int k0 = c*32;
        #pragma unroll
        for (int i=0;i<2;i++){
            int id  = tid + i*256;
            int row = id >> 2, cc = id & 3;
            uint32_t d = row*64 + ((cc ^ ((row>>1)&3))<<4);
            size_t ga = (size_t)(bm+row)*K + k0 + cc*8;
            size_t gb = (size_t)(bn+row)*K + k0 + cc*8;
            cp16(so          + d, Ah + ga);
            cp16(so +  8192  + d, Al + ga);
            cp16(so + 16384  + d, B  + gb);
        }
        asm volatile("cp.async.commit_group;");
    };

    const int NK = K >> 5;
    load_stage(0);
    load_stage(1);

    for (int it = 0; it < NK; it++) {
        __syncthreads();
        if (it + 2 < NK) {
            load_stage(it + 2);
            asm volatile("cp.async.wait_group 2;");
        } else if (it + 1 < NK) {
            asm volatile("cp.async.wait_group 1;");
        } else {
            asm volatile("cp.async.wait_group 0;");
        }
        __syncthreads();

        uint32_t so = sbase + (it % NSTG)*STG_BYTES;
        #pragma unroll
        for (int ks=0; ks<2; ks++){
            unsigned ah[4][4], al[4][4], bf[4][2];
            #pragma unroll
            for (int mt=0; mt<4; mt++){
                int row = wm + mt*16 + (lane&15);
                int ch  = ks*2 + (lane>>4);
                uint32_t off = row*64 + ((ch ^ ((row>>1)&3))<<4);
                ldsm4(ah[mt], so + off);
                ldsm4(al[mt], so + 8192 + off);
            }
            #pragma unroll
            for (int nt=0; nt<4; nt++){
                int row = wn + nt*8 + (lane&7);
                int ch  = ks*2 + ((lane&15)>>3);
                uint32_t off = row*64 + ((ch ^ ((row>>1)&3))<<4);
                ldsm2(bf[nt], so + 16384 + off);
            }
            #pragma unroll
            for (int mt=0; mt<4; mt++)
              #pragma unroll
              for (int nt=0; nt<4; nt++){
                  mma_f16(acc[mt][nt], ah[mt], bf[nt]);
                  mma_f16(acc[mt][nt], al[mt], bf[nt]);
              }
        }
    }

    #pragma unroll
    for (int mt=0; mt<4; mt++){
        int r = bm + wm + mt*16 + (lane>>2);
        #pragma unroll
        for (int nt=0; nt<4; nt++){
            int c = bn + wn + nt*8 + (lane&3)*2;
            *(float2*)(C + (size_t) r   *N + c) = make_float2(acc[mt][nt][0], acc[mt][nt][1]);
            *(float2*)(C + (size_t)(r+8)*N + c) = make_float2(acc[mt][nt][2], acc[mt][nt][3]);
        }
    }
}

// ------------ elementwise fp32 -> fp16 hi/lo split ------------
__global__ __launch_bounds__(256) void split_ew(const float* __restrict__ in,
                                                __half* __restrict__ oh,
                                                __half* __restrict__ ol,
                                                size_t n4) {
    size_t i = (size_t)blockIdx.x*256 + threadIdx.x;
    size_t stride = (size_t)gridDim.x*256;
    for (; i < n4; i += stride) {
        float4 v = ((const float4*)in)[i];
        __half h0=__float2half_rn(v.x), h1=__float2half_rn(v.y),
               h2=__float2half_rn(v.z), h3=__float2half_rn(v.w);
        __half2 H0 = {h0,h1}, H1 = {h2,h3};
        __half2 L0 = {__float2half_rn(v.x-__half2float(h0)),
                      __float2half_rn(v.y-__half2float(h1))};
        __half2 L1 = {__float2half_rn(v.z-__half2float(h2)),
                      __float2half_rn(v.w-__half2float(h3))};
        ((__half2*)oh)[2*i]   = H0; ((__half2*)oh)[2*i+1] = H1;
        ((__half2*)ol)[2*i]   = L0; ((__half2*)ol)[2*i+1] = L1;
    }
}

// ------------ transpose + round: in[K][N] fp32 -> out[n][k] fp16 ------------
__global__ __launch_bounds__(256) void splitT(const float* __restrict__ in,
                                              __half* __restrict__ oh,
                                              int K, int N) {
    __shared__ float tile[32][33];
    int n0 = blockIdx.x*32, k0 = blockIdx.y*32;
    int tx = threadIdx.x & 31, ty = threadIdx.x >> 5;
    #pragma unroll
    for (int j = 0; j < 32; j += 8)
        tile[ty+j][tx] = in[(size_t)(k0+ty+j)*N + n0 + tx];
    __syncthreads();
    #pragma unroll
    for (int j = 0; j < 32; j += 8)
        oh[(size_t)(n0+ty+j)*K + k0 + tx] = __float2half_rn(tile[tx][ty+j]);
}

// ------------ ba = H @ W_ba ------------
__global__ __launch_bounds__(256) void gemm_ba(const float* __restrict__ A,
                                               const float* __restrict__ B) {
    int r = blockIdx.x*4 + (threadIdx.x>>6);
    int c = threadIdx.x & 63;
    const float* ar = A + (size_t)r*HID;
    float acc = 0.f;
    #pragma unroll 4
    for (int k=0;k<HID;k+=4){
        float4 a = *(const float4*)(ar+k);
        acc += a.x*B[(k  )*64+c] + a.y*B[(k+1)*64+c]
             + a.z*B[(k+2)*64+c] + a.w*B[(k+3)*64+c];
    }
    g_ba[r*64+c] = acc;
}

// ------------ causal depthwise conv(4) + silu ------------
__global__ __launch_bounds__(128) void conv_kernel(const float* __restrict__ cw) {
    int c  = blockIdx.x*128 + threadIdx.x;
    int t0 = blockIdx.y*64;
    int col;
    if (c < 2048)      col = (c>>7)*768 + (c&127);
    else if (c < 4096) { int cc=c-2048; col = (cc>>7)*768 + 128 + (cc&127); }
    else               { int cc=c-4096; col = (cc>>8)*768 + 256 + (cc&255); }
    float4 w = *(const float4*)(cw + c*4);
    float x0=0.f, x1=0.f, x2=0.f;
    if (t0 >= 3) {
        x0 = g_qkvz[(size_t)(t0-3)*NQKVZ + col];
        x1 = g_qkvz[(size_t)(t0-2)*NQKVZ + col];
        x2 = g_qkvz[(size_t)(t0-1)*NQKVZ + col];
    }
    #pragma unroll 4
    for (int t=t0; t<t0+64; t++) {
        float x3 = g_qkvz[(size_t)t*NQKVZ + col];
        float y = x0*w.x + x1*w.y + x2*w.z + x3*w.w;
        g_mixed[(size_t)t*CONVD + c] = y / (1.f + expf(-y));
        x0=x1; x1=x2; x2=x3;
    }
}

// ------------ l2norm q/k, gates ------------
__global__ __launch_bounds__(256) void prep_kernel(const float* __restrict__ Alog,
                                                   const float* __restrict__ dtb) {
    int t = blockIdx.x;
    int warp = threadIdx.x>>5, lane = threadIdx.x&31;
    #pragma unroll
    for (int i=0;i<4;i++){
        int row = warp*4+i;
        int isK = row>=16, h = row&15;
        const float* src = g_mixed + (size_t)t*CONVD + (isK?2048:0) + h*128;
        float4 v = *(const float4*)(src + lane*4);
        float ss = v.x*v.x+v.y*v.y+v.z*v.z+v.w*v.w;
        ss += __shfl_xor_sync(~0u, ss, 16);
        ss += __shfl_xor_sync(~0u, ss, 8);
        ss += __shfl_xor_sync(~0u, ss, 4);
        ss += __shfl_xor_sync(~0u, ss, 2);
        ss += __shfl_xor_sync(~0u, ss, 1);
        float sc = rsqrtf(ss + 1e-6f);
        if (!isK) sc *= 0.08838834764831845f;
        float* dst = (isK ? g_kn : g_qn) + (size_t)t*KEYDIM + h*128 + lane*4;
        *(float4*)dst = make_float4(v.x*sc, v.y*sc, v.z*sc, v.w*sc);
    }
    if (threadIdx.x < 32) {
        int h32 = threadIdx.x, h16 = h32>>1, j = h32&1;
        float b = g_ba[t*64 + h16*4 + j];
        float a = g_ba[t*64 + h16*4 + 2 + j];
        float x = a + dtb[h32];
        float sp = (x > 20.f) ? x : log1pf(expf(x));
        g_eg  [t*32 + h32] = expf(-expf(Alog[h32]) * sp);
        g_beta[t*32 + h32] = 1.f / (1.f + expf(-b));
    }
}

// ------------ gated delta-rule scan: smem ring + off-critical-path output ------------
// block = (h, vb); 4 warps x 4 v-columns; lane = (vg=lane>>3, kg=lane&7).
// Per-warp private smem ring (depth 6): k 512B | q 512B | v4 16B | e 4B | b 4B.
#define SD 6
#define SLOT 1088
__global__ __launch_bounds__(128) void scan_kernel() {
    __shared__ __align__(16) char ring[4][SD][SLOT];
    int h = blockIdx.x>>3, vb = blockIdx.x&7;
    int warp = threadIdx.x>>5, lane = threadIdx.x&31;
    int kg = lane&7, vg = lane>>3;
    int v0 = vb*16 + warp*4;
    int h16 = h>>1;
    const char* kbase = (const char*)(g_kn + h16*128);
    const char* qbase = (const char*)(g_qn + h16*128);
    const char* vbase = (const char*)(g_mixed + 4096 + h*128 + v0);
    float* op = g_core + h*128 + v0 + vg;
    uint32_t rb = (uint32_t)__cvta_generic_to_shared(&ring[warp][0][0]);

    auto load_slot = [&](int t){
        uint32_t so = rb + (t % SD)*SLOT;
        cp16(so + lane*16,       kbase + (size_t)t*KEYDIM*4 + lane*16);
        cp16(so + 512 + lane*16, qbase + (size_t)t*KEYDIM*4 + lane*16);
        if (lane == 0) cp16(so + 1024, vbase + (size_t)t*CONVD*4);
        if (lane == 1) cp4 (so + 1040, g_eg   + (size_t)t*32 + h);
        if (lane == 2) cp4 (so + 1044, g_beta + (size_t)t*32 + h);
        asm volatile("cp.async.commit_group;" ::: "memory");
    };

    #pragma unroll
    for (int t = 0; t < SD-1; t++) load_slot(t);

    ull s[8];
    #pragma unroll
    for (int i=0;i<8;i++) s[i]=0ull;

    for (int t = 0; t < SEQ; t++) {
        asm volatile("cp.async.wait_group %0;" :: "n"(SD-2) : "memory");
        __syncwarp();

        const char* slot = &ring[warp][t % SD][0];
        const ulonglong2* kk = (const ulonglong2*)(slot + kg*64);
        const ulonglong2* qq = (const ulonglong2*)(slot + 512 + kg*64);
        ull kf[8], qf[8];
        #pragma unroll
        for (int i=0;i<4;i++){
            ulonglong2 a = kk[i]; kf[2*i]=a.x; kf[2*i+1]=a.y;
            ulonglong2 b = qq[i]; qf[2*i]=b.x; qf[2*i+1]=b.y;
        }
        float vv = ((const float*)(slot + 1024))[vg];
        float ee = *(const float*)(slot + 1040);
        float bt = *(const float*)(slot + 1044);

        // three parallel reductions over this lane's 16 rows
        ull pa0 = fma2(s[1],kf[1], mul2(s[0],kf[0]));
        ull pa1 = fma2(s[3],kf[3], mul2(s[2],kf[2]));
        ull pa2 = fma2(s[5],kf[5], mul2(s[4],kf[4]));
        ull pa3 = fma2(s[7],kf[7], mul2(s[6],kf[6]));
        ull pb0 = fma2(s[1],qf[1], mul2(s[0],qf[0]));
        ull pb1 = fma2(s[3],qf[3], mul2(s[2],qf[2]));
        ull pb2 = fma2(s[5],qf[5], mul2(s[4],qf[4]));
        ull pb3 = fma2(s[7],qf[7], mul2(s[6],qf[6]));
        ull pc0 = fma2(kf[1],qf[1], mul2(kf[0],qf[0]));
        ull pc1 = fma2(kf[3],qf[3], mul2(kf[2],qf[2]));
        ull pc2 = fma2(kf[5],qf[5], mul2(kf[4],qf[4]));
        ull pc3 = fma2(kf[7],qf[7], mul2(kf[6],qf[6]));
        pa0 = add2(add2(pa0,pa1), add2(pa2,pa3));
        pb0 = add2(add2(pb0,pb1), add2(pb2,pb3));
        pc0 = add2(add2(pc0,pc1), add2(pc2,pc3));
        float ax, ay, bx, by, cx, cy;
        upk2(pa0, ax, ay); upk2(pb0, bx, by); upk2(pc0, cx, cy);
        float rk = ax + ay, rq = bx + by, rkq = cx + cy;
        #pragma unroll
        for (int m = 1; m <= 4; m <<= 1) {
            rk  += __shfl_xor_sync(~0u, rk,  m);
            rq  += __shfl_xor_sync(~0u, rq,  m);
            rkq += __shfl_xor_sync(~0u, rkq, m);
        }
        float delta = (vv - ee*rk) * bt;
        float o = ee*rq + rkq*delta;
        ull e2 = pk2(ee, ee), d2 = pk2(delta, delta);
        #pragma unroll
        for (int i=0;i<8;i++) s[i] = fma2(s[i], e2, mul2(kf[i], d2));
        if (kg == 0) op[(size_t)t*VALDIM] = o;

        if (t + SD-1 < SEQ) load_slot(t + SD-1);
        else asm volatile("cp.async.commit_group;" ::: "memory");
    }
}

// ------------ RMS norm + silu(z) gate (fused fp16 split output) ------------
__global__ __launch_bounds__(256) void gate_kernel(const float* __restrict__ nw) {
    int t = blockIdx.x;
    int warp = threadIdx.x>>5, lane = threadIdx.x&31;
    #pragma unroll
    for (int i=0;i<4;i++){
        int h = warp*4 + i;
        const float* cp = g_core + (size_t)t*VALDIM + h*128;
        float4 c = *(const float4*)(cp + lane*4);
        float ss = c.x*c.x + c.y*c.y + c.z*c.z + c.w*c.w;
        ss += __shfl_xor_sync(~0u, ss, 16);
        ss += __shfl_xor_sync(~0u, ss, 8);
        ss += __shfl_xor_sync(~0u, ss, 4);
        ss += __shfl_xor_sync(~0u, ss, 2);
        ss += __shfl_xor_sync(~0u, ss, 1);
        float sc = rsqrtf(ss*(1.f/128.f) + 1e-6f);
        const float* zp = g_qkvz + (size_t)t*NQKVZ + (h>>1)*768 + 512 + (h&1)*128;
        float4 z = *(const float4*)(zp + lane*4);
        float4 w = *(const float4*)(nw + lane*4);
        float4 o;
        o.x = c.x*sc*w.x * (z.x/(1.f+expf(-z.x)));
        o.y = c.y*sc*w.y * (z.y/(1.f+expf(-z.y)));
        o.z = c.z*sc*w.z * (z.z/(1.f+expf(-z.z)));
        o.w = c.w*sc*w.w * (z.w/(1.f+expf(-z.w)));
        size_t base = (size_t)t*VALDIM + h*128 + lane*4;
        __half h0=__float2half_rn(o.x), h1=__float2half_rn(o.y),
               h2=__float2half_rn(o.z), h3=__float2half_rn(o.w);
        __half2 H0={h0,h1}, H1={h2,h3};
        __half2 L0={__float2half_rn(o.x-__half2float(h0)), __float2half_rn(o.y-__half2float(h1))};
        __half2 L1={__float2half_rn(o.z-__half2float(h2)), __float2half_rn(o.w-__half2float(h3))};
        *(__half2*)(g_Gh + base)     = H0; *(__half2*)(g_Gh + base + 2) = H1;
        *(__half2*)(g_Gl + base)     = L0; *(__half2*)(g_Gl + base + 2) = L1;
    }
}

extern "C" void kernel_launch(void* const* d_in, const int* in_sizes, int n_in,
                              void* d_out, int out_size) {
    const float* H     = (const float*)d_in[0];
    const float* Wqkvz = (const float*)d_in[1];
    const float* Wba   = (const float*)d_in[2];
    const float* convw = (const float*)d_in[3];
    const float* Alog  = (const float*)d_in[4];
    const float* dtb   = (const float*)d_in[5];
    const float* nw    = (const float*)d_in[6];
    const float* Wout  = (const float*)d_in[7];
    float* out = (float*)d_out;

    float *qkvz;
    __half *Hh,*Hl,*W1,*Gh,*Gl,*W2;
    cudaGetSymbolAddress((void**)&qkvz, g_qkvz);
    cudaGetSymbolAddress((void**)&Hh, g_Hh); cudaGetSymbolAddress((void**)&Hl, g_Hl);
    cudaGetSymbolAddress((void**)&W1, g_W1);
    cudaGetSymbolAddress((void**)&Gh, g_Gh); cudaGetSymbolAddress((void**)&Gl, g_Gl);
    cudaGetSymbolAddress((void**)&W2, g_W2);

    static int smem_set = 0;
    if (!smem_set) {
        cudaFuncSetAttribute(gemm_sp, cudaFuncAttributeMaxDynamicSharedMemorySize, NSTG*STG_BYTES);
        smem_set = 1;
    }

    split_ew<<<1024, 256>>>(H, Hh, Hl, (size_t)SEQ*HID/4);
    splitT  <<<dim3(NQKVZ/32, HID/32), 256>>>(Wqkvz, W1, HID, NQKVZ);
    splitT  <<<dim3(HID/32, VALDIM/32), 256>>>(Wout, W2, VALDIM, HID);

    gemm_sp<<<dim3(SEQ/128, NQKVZ/128), 256, NSTG*STG_BYTES>>>(Hh, Hl, W1, qkvz, SEQ, NQKVZ, HID);
    gemm_ba<<<SEQ/4, 256>>>(H, Wba);
    conv_kernel<<<dim3(CONVD/128, SEQ/64), 128>>>(convw);
    prep_kernel<<<SEQ, 256>>>(Alog, dtb);
    scan_kernel<<<256, 128>>>();
    gate_kernel<<<SEQ, 256>>>(nw);

    gemm_sp<<<dim3(SEQ/128, HID/128), 256, NSTG*STG_BYTES>>>(Gh, Gl, W2, out, SEQ, HID, VALDIM);
}

// round 16
// speedup vs baseline: 1.4021x; 1.4021x over previous
#include <cuda_runtime.h>
#include <cuda_bf16.h>
#include <cuda_fp16.h>
#include <cstdint>

#define SEQ   4096
#define HID   2048
#define NQKVZ 12288
#define CONVD 8192
#define KEYDIM 2048
#define VALDIM 4096

typedef unsigned long long ull;

// ------------ scratch ------------
__device__ float g_qkvz [(size_t)SEQ * NQKVZ];
__device__ float g_ba   [SEQ * 64];
__device__ float g_mixed[(size_t)SEQ * CONVD];
__device__ float g_qn   [(size_t)SEQ * KEYDIM];
__device__ float g_kn   [(size_t)SEQ * KEYDIM];
__device__ float g_eg   [SEQ * 32];
__device__ float g_beta [SEQ * 32];
__device__ float g_core [(size_t)SEQ * VALDIM];

__device__ __half g_Hh [(size_t)SEQ * HID];
__device__ __half g_Hl [(size_t)SEQ * HID];
__device__ __half g_W1 [(size_t)NQKVZ * HID];
__device__ __half g_Gh [(size_t)SEQ * VALDIM];
__device__ __half g_Gl [(size_t)SEQ * VALDIM];
__device__ __half g_W2 [(size_t)HID * VALDIM];

// ------------ f32x2 helpers ------------
__device__ __forceinline__ ull pk2(float a, float b){ ull r; asm("mov.b64 %0,{%1,%2};":"=l"(r):"f"(a),"f"(b)); return r; }
__device__ __forceinline__ void upk2(ull v, float& a, float& b){ asm("mov.b64 {%0,%1},%2;":"=f"(a),"=f"(b):"l"(v)); }
__device__ __forceinline__ ull fma2(ull a, ull b, ull c){ ull d; asm("fma.rn.f32x2 %0,%1,%2,%3;":"=l"(d):"l"(a),"l"(b),"l"(c)); return d; }
__device__ __forceinline__ ull mul2(ull a, ull b){ ull d; asm("mul.rn.f32x2 %0,%1,%2;":"=l"(d):"l"(a),"l"(b)); return d; }
__device__ __forceinline__ ull add2(ull a, ull b){ ull d; asm("add.rn.f32x2 %0,%1,%2;":"=l"(d):"l"(a),"l"(b)); return d; }

__device__ __forceinline__ void mma_f16(float* c, const unsigned* a, const unsigned* b){
    asm volatile("mma.sync.aligned.m16n8k16.row.col.f32.f16.f16.f32 "
        "{%0,%1,%2,%3},{%4,%5,%6,%7},{%8,%9},{%0,%1,%2,%3};\n"
        : "+f"(c[0]),"+f"(c[1]),"+f"(c[2]),"+f"(c[3])
        : "r"(a[0]),"r"(a[1]),"r"(a[2]),"r"(a[3]),"r"(b[0]),"r"(b[1]));
}
__device__ __forceinline__ void cp16(uint32_t dst, const void* src){
    asm volatile("cp.async.cg.shared.global [%0], [%1], 16;" :: "r"(dst), "l"(src));
}
__device__ __forceinline__ void cp4(uint32_t dst, const void* src){
    asm volatile("cp.async.ca.shared.global [%0], [%1], 4;" :: "r"(dst), "l"(src));
}
__device__ __forceinline__ void ldsm4(unsigned* r, uint32_t a){
    asm volatile("ldmatrix.sync.aligned.m8n8.x4.shared.b16 {%0,%1,%2,%3},[%4];"
        : "=r"(r[0]),"=r"(r[1]),"=r"(r[2]),"=r"(r[3]) : "r"(a));
}
__device__ __forceinline__ void ldsm2(unsigned* r, uint32_t a){
    asm volatile("ldmatrix.sync.aligned.m8n8.x2.shared.b16 {%0,%1},[%2];"
        : "=r"(r[0]),"=r"(r[1]) : "r"(a));
}

// ------------ 3-stage pipelined split-fp16 GEMM (R13, unchanged) ------------
#define STG_BYTES 24576
#define NSTG 3
__global__ __launch_bounds__(256, 2) void gemm_sp(const __half* __restrict__ Ah,
                                                  const __half* __restrict__ Al,
                                                  const __half* __restrict__ B,
                                                  float* __restrict__ C,
                                                  int M, int N, int K) {
    extern __shared__ char smem[];
    uint32_t sbase = (uint32_t)__cvta_generic_to_shared(smem);
    const int tid = threadIdx.x;
    const int bm = blockIdx.x*128, bn = blockIdx.y*128;
    const int warp = tid >> 5, lane = tid & 31;
    const int wm = (warp >> 2)*64, wn = (warp & 3)*32;

    float acc[4][4][4];
    #pragma unroll
    for (int i=0;i<4;i++)
      #pragma unroll
      for (int j=0;j<4;j++)
        #pragma unroll
        for (int k=0;k<4;k++) acc[i][j][k]=0.f;

    auto load_stage = [&](int c){
        uint32_t so = sbase + (c % NSTG)*STG_BYTES;
        int k0 = c*32;
        #pragma unroll
        for (int i=0;i<2;i++){
            int id  = tid + i*256;
            int row = id >> 2, cc = id & 3;
            uint32_t d = row*64 + ((cc ^ ((row>>1)&3))<<4);
            size_t ga = (size_t)(bm+row)*K + k0 + cc*8;
            size_t gb = (size_t)(bn+row)*K + k0 + cc*8;
            cp16(so          + d, Ah + ga);
            cp16(so +  8192  + d, Al + ga);
            cp16(so + 16384  + d, B  + gb);
        }
        asm volatile("cp.async.commit_group;");
    };

    const int NK = K >> 5;
    load_stage(0);
    load_stage(1);

    for (int it = 0; it < NK; it++) {
        __syncthreads();
        if (it + 2 < NK) {
            load_stage(it + 2);
            asm volatile("cp.async.wait_group 2;");
        } else if (it + 1 < NK) {
            asm volatile("cp.async.wait_group 1;");
        } else {
            asm volatile("cp.async.wait_group 0;");
        }
        __syncthreads();

        uint32_t so = sbase + (it % NSTG)*STG_BYTES;
        #pragma unroll
        for (int ks=0; ks<2; ks++){
            unsigned ah[4][4], al[4][4], bf[4][2];
            #pragma unroll
            for (int mt=0; mt<4; mt++){
                int row = wm + mt*16 + (lane&15);
                int ch  = ks*2 + (lane>>4);
                uint32_t off = row*64 + ((ch ^ ((row>>1)&3))<<4);
                ldsm4(ah[mt], so + off);
                ldsm4(al[mt], so + 8192 + off);
            }
            #pragma unroll
            for (int nt=0; nt<4; nt++){
                int row = wn + nt*8 + (lane&7);
                int ch  = ks*2 + ((lane&15)>>3);
                uint32_t off = row*64 + ((ch ^ ((row>>1)&3))<<4);
                ldsm2(bf[nt], so + 16384 + off);
            }
            #pragma unroll
            for (int mt=0; mt<4; mt++)
              #pragma unroll
              for (int nt=0; nt<4; nt++){
                  mma_f16(acc[mt][nt], ah[mt], bf[nt]);
                  mma_f16(acc[mt][nt], al[mt], bf[nt]);
              }
        }
    }

    #pragma unroll
    for (int mt=0; mt<4; mt++){
        int r = bm + wm + mt*16 + (lane>>2);
        #pragma unroll
        for (int nt=0; nt<4; nt++){
            int c = bn + wn + nt*8 + (lane&3)*2;
            *(float2*)(C + (size_t) r   *N + c) = make_float2(acc[mt][nt][0], acc[mt][nt][1]);
            *(float2*)(C + (size_t)(r+8)*N + c) = make_float2(acc[mt][nt][2], acc[mt][nt][3]);
        }
    }
}

// ------------ elementwise fp32 -> fp16 hi/lo split ------------
__global__ __launch_bounds__(256) void split_ew(const float* __restrict__ in,
                                                __half* __restrict__ oh,
                                                __half* __restrict__ ol,
                                                size_t n4) {
    size_t i = (size_t)blockIdx.x*256 + threadIdx.x;
    size_t stride = (size_t)gridDim.x*256;
    for (; i < n4; i += stride) {
        float4 v = ((const float4*)in)[i];
        __half h0=__float2half_rn(v.x), h1=__float2half_rn(v.y),
               h2=__float2half_rn(v.z), h3=__float2half_rn(v.w);
        __half2 H0 = {h0,h1}, H1 = {h2,h3};
        __half2 L0 = {__float2half_rn(v.x-__half2float(h0)),
                      __float2half_rn(v.y-__half2float(h1))};
        __half2 L1 = {__float2half_rn(v.z-__half2float(h2)),
                      __float2half_rn(v.w-__half2float(h3))};
        ((__half2*)oh)[2*i]   = H0; ((__half2*)oh)[2*i+1] = H1;
        ((__half2*)ol)[2*i]   = L0; ((__half2*)ol)[2*i+1] = L1;
    }
}

// ------------ transpose + round: in[K][N] fp32 -> out[n][k] fp16 ------------
__global__ __launch_bounds__(256) void splitT(const float* __restrict__ in,
                                              __half* __restrict__ oh,
                                              int K, int N) {
    __shared__ float tile[32][33];
    int n0 = blockIdx.x*32, k0 = blockIdx.y*32;
    int tx = threadIdx.x & 31, ty = threadIdx.x >> 5;
    #pragma unroll
    for (int j = 0; j < 32; j += 8)
        tile[ty+j][tx] = in[(size_t)(k0+ty+j)*N + n0 + tx];
    __syncthreads();
    #pragma unroll
    for (int j = 0; j < 32; j += 8)
        oh[(size_t)(n0+ty+j)*K + k0 + tx] = __float2half_rn(tile[tx][ty+j]);
}

// ------------ ba = H @ W_ba ------------
__global__ __launch_bounds__(256) void gemm_ba(const float* __restrict__ A,
                                               const float* __restrict__ B) {
    int r = blockIdx.x*4 + (threadIdx.x>>6);
    int c = threadIdx.x & 63;
    const float* ar = A + (size_t)r*HID;
    float acc = 0.f;
    #pragma unroll 4
    for (int k=0;k<HID;k+=4){
        float4 a = *(const float4*)(ar+k);
        acc += a.x*B[(k  )*64+c] + a.y*B[(k+1)*64+c]
             + a.z*B[(k+2)*64+c] + a.w*B[(k+3)*64+c];
    }
    g_ba[r*64+c] = acc;
}

// ------------ causal depthwise conv(4) + silu ------------
__global__ __launch_bounds__(128) void conv_kernel(const float* __restrict__ cw) {
    int c  = blockIdx.x*128 + threadIdx.x;
    int t0 = blockIdx.y*64;
    int col;
    if (c < 2048)      col = (c>>7)*768 + (c&127);
    else if (c < 4096) { int cc=c-2048; col = (cc>>7)*768 + 128 + (cc&127); }
    else               { int cc=c-4096; col = (cc>>8)*768 + 256 + (cc&255); }
    float4 w = *(const float4*)(cw + c*4);
    float x0=0.f, x1=0.f, x2=0.f;
    if (t0 >= 3) {
        x0 = g_qkvz[(size_t)(t0-3)*NQKVZ + col];
        x1 = g_qkvz[(size_t)(t0-2)*NQKVZ + col];
        x2 = g_qkvz[(size_t)(t0-1)*NQKVZ + col];
    }
    #pragma unroll 4
    for (int t=t0; t<t0+64; t++) {
        float x3 = g_qkvz[(size_t)t*NQKVZ + col];
        float y = x0*w.x + x1*w.y + x2*w.z + x3*w.w;
        g_mixed[(size_t)t*CONVD + c] = y / (1.f + expf(-y));
        x0=x1; x1=x2; x2=x3;
    }
}

// ------------ l2norm q/k, gates ------------
__global__ __launch_bounds__(256) void prep_kernel(const float* __restrict__ Alog,
                                                   const float* __restrict__ dtb) {
    int t = blockIdx.x;
    int warp = threadIdx.x>>5, lane = threadIdx.x&31;
    #pragma unroll
    for (int i=0;i<4;i++){
        int row = warp*4+i;
        int isK = row>=16, h = row&15;
        const float* src = g_mixed + (size_t)t*CONVD + (isK?2048:0) + h*128;
        float4 v = *(const float4*)(src + lane*4);
        float ss = v.x*v.x+v.y*v.y+v.z*v.z+v.w*v.w;
        ss += __shfl_xor_sync(~0u, ss, 16);
        ss += __shfl_xor_sync(~0u, ss, 8);
        ss += __shfl_xor_sync(~0u, ss, 4);
        ss += __shfl_xor_sync(~0u, ss, 2);
        ss += __shfl_xor_sync(~0u, ss, 1);
        float sc = rsqrtf(ss + 1e-6f);
        if (!isK) sc *= 0.08838834764831845f;
        float* dst = (isK ? g_kn : g_qn) + (size_t)t*KEYDIM + h*128 + lane*4;
        *(float4*)dst = make_float4(v.x*sc, v.y*sc, v.z*sc, v.w*sc);
    }
    if (threadIdx.x < 32) {
        int h32 = threadIdx.x, h16 = h32>>1, j = h32&1;
        float b = g_ba[t*64 + h16*4 + j];
        float a = g_ba[t*64 + h16*4 + 2 + j];
        float x = a + dtb[h32];
        float sp = (x > 20.f) ? x : log1pf(expf(x));
        g_eg  [t*32 + h32] = expf(-expf(Alog[h32]) * sp);
        g_beta[t*32 + h32] = 1.f / (1.f + expf(-b));
    }
}

// ------------ gated delta-rule scan: block-level cp.async ring, depth 8 ------------
// block = (h, vb: 16 v-cols); 4 warps x 4 cols; lane = (vg=lane>>3, kg=lane&7).
// slot (1152B): k 512B (chunk c at 16*(c^(c>>3))) | q 512B same | v 64B | e | b
// contract per step: wait_group 6 (own slot-t group done) -> __syncthreads
// (others' writes visible) -> read slot t -> issue slot t+7.
#define SCD 8
#define SCSLOT 1152
__global__ __launch_bounds__(128) void scan_kernel() {
    __shared__ __align__(16) char ring[SCD*SCSLOT];
    const int tid = threadIdx.x;
    const int h = blockIdx.x>>3, vb = blockIdx.x&7;
    const int warp = tid>>5, lane = tid&31;
    const int kg = lane&7, vg = lane>>3;
    const int h16 = h>>1;
    const char* kbase = (const char*)(g_kn + h16*128);
    const char* qbase = (const char*)(g_qn + h16*128);
    const char* vbase = (const char*)(g_mixed + 4096 + h*128 + vb*16);
    float* op = g_core + h*128 + vb*16 + warp*4 + vg;
    const uint32_t rb = (uint32_t)__cvta_generic_to_shared(ring);

    auto load_slot = [&](int t){
        uint32_t so = rb + (t & (SCD-1))*SCSLOT;
        if (tid < 32) {
            cp16(so + ((tid ^ (tid>>3))<<4), kbase + (size_t)t*KEYDIM*4 + tid*16);
        } else if (tid < 64) {
            int c = tid - 32;
            cp16(so + 512 + ((c ^ (c>>3))<<4), qbase + (size_t)t*KEYDIM*4 + c*16);
        } else if (tid < 68) {
            cp16(so + 1024 + (tid-64)*16, vbase + (size_t)t*CONVD*4 + (tid-64)*16);
        } else if (tid == 68) {
            cp4(so + 1088, g_eg + (size_t)t*32 + h);
        } else if (tid == 69) {
            cp4(so + 1092, g_beta + (size_t)t*32 + h);
        }
        asm volatile("cp.async.commit_group;" ::: "memory");
    };

    #pragma unroll
    for (int t = 0; t < SCD-1; t++) load_slot(t);

    ull s[8];
    #pragma unroll
    for (int i=0;i<8;i++) s[i]=0ull;

    for (int t = 0; t < SEQ; t++) {
        asm volatile("cp.async.wait_group %0;" :: "n"(SCD-2) : "memory");
        __syncthreads();

        const char* slot = ring + (t & (SCD-1))*SCSLOT;
        ull kf[8], qf[8];
        #pragma unroll
        for (int i=0;i<4;i++){
            int c  = kg*4 + i;
            int sw = c ^ (kg>>1);
            ulonglong2 a = *(const ulonglong2*)(slot + (sw<<4));
            ulonglong2 b = *(const ulonglong2*)(slot + 512 + (sw<<4));
            kf[2*i]=a.x; kf[2*i+1]=a.y;
            qf[2*i]=b.x; qf[2*i+1]=b.y;
        }
        float vv = ((const float*)(slot + 1024))[warp*4 + vg];
        float ee = *(const float*)(slot + 1088);
        float bt = *(const float*)(slot + 1092);

        // three parallel 16-row reductions (S^T k, S^T q, k.q)
        ull pa0 = fma2(s[1],kf[1], mul2(s[0],kf[0]));
        ull pa1 = fma2(s[3],kf[3], mul2(s[2],kf[2]));
        ull pa2 = fma2(s[5],kf[5], mul2(s[4],kf[4]));
        ull pa3 = fma2(s[7],kf[7], mul2(s[6],kf[6]));
        ull pb0 = fma2(s[1],qf[1], mul2(s[0],qf[0]));
        ull pb1 = fma2(s[3],qf[3], mul2(s[2],qf[2]));
        ull pb2 = fma2(s[5],qf[5], mul2(s[4],qf[4]));
        ull pb3 = fma2(s[7],qf[7], mul2(s[6],qf[6]));
        ull pc0 = fma2(kf[1],qf[1], mul2(kf[0],qf[0]));
        ull pc1 = fma2(kf[3],qf[3], mul2(kf[2],qf[2]));
        ull pc2 = fma2(kf[5],qf[5], mul2(kf[4],qf[4]));
        ull pc3 = fma2(kf[7],qf[7], mul2(kf[6],qf[6]));
        pa0 = add2(add2(pa0,pa1), add2(pa2,pa3));
        pb0 = add2(add2(pb0,pb1), add2(pb2,pb3));
        pc0 = add2(add2(pc0,pc1), add2(pc2,pc3));
        float ax, ay, bx, by, cx, cy;
        upk2(pa0, ax, ay); upk2(pb0, bx, by); upk2(pc0, cx, cy);
        float rk = ax + ay, rq = bx + by, rkq = cx + cy;
        #pragma unroll
        for (int m = 1; m <= 4; m <<= 1) {
            rk  += __shfl_xor_sync(~0u, rk,  m);
            rq  += __shfl_xor_sync(~0u, rq,  m);
            rkq += __shfl_xor_sync(~0u, rkq, m);
        }
        float delta = (vv - ee*rk) * bt;
        float o = ee*rq + rkq*delta;
        ull e2 = pk2(ee, ee), d2 = pk2(delta, delta);
        #pragma unroll
        for (int i=0;i<8;i++) s[i] = fma2(s[i], e2, mul2(kf[i], d2));
        if (kg == 0) op[(size_t)t*VALDIM] = o;

        if (t + SCD-1 < SEQ) load_slot(t + SCD-1);
        else asm volatile("cp.async.commit_group;" ::: "memory");
    }
}

// ------------ RMS norm + silu(z) gate (fused fp16 split output) ------------
__global__ __launch_bounds__(256) void gate_kernel(const float* __restrict__ nw) {
    int t = blockIdx.x;
    int warp = threadIdx.x>>5, lane = threadIdx.x&31;
    #pragma unroll
    for (int i=0;i<4;i++){
        int h = warp*4 + i;
        const float* cp = g_core + (size_t)t*VALDIM + h*128;
        float4 c = *(const float4*)(cp + lane*4);
        float ss = c.x*c.x + c.y*c.y + c.z*c.z + c.w*c.w;
        ss += __shfl_xor_sync(~0u, ss, 16);
        ss += __shfl_xor_sync(~0u, ss, 8);
        ss += __shfl_xor_sync(~0u, ss, 4);
        ss += __shfl_xor_sync(~0u, ss, 2);
        ss += __shfl_xor_sync(~0u, ss, 1);
        float sc = rsqrtf(ss*(1.f/128.f) + 1e-6f);
        const float* zp = g_qkvz + (size_t)t*NQKVZ + (h>>1)*768 + 512 + (h&1)*128;
        float4 z = *(const float4*)(zp + lane*4);
        float4 w = *(const float4*)(nw + lane*4);
        float4 o;
        o.x = c.x*sc*w.x * (z.x/(1.f+expf(-z.x)));
        o.y = c.y*sc*w.y * (z.y/(1.f+expf(-z.y)));
        o.z = c.z*sc*w.z * (z.z/(1.f+expf(-z.z)));
        o.w = c.w*sc*w.w * (z.w/(1.f+expf(-z.w)));
        size_t base = (size_t)t*VALDIM + h*128 + lane*4;
        __half h0=__float2half_rn(o.x), h1=__float2half_rn(o.y),
               h2=__float2half_rn(o.z), h3=__float2half_rn(o.w);
        __half2 H0={h0,h1}, H1={h2,h3};
        __half2 L0={__float2half_rn(o.x-__half2float(h0)), __float2half_rn(o.y-__half2float(h1))};
        __half2 L1={__float2half_rn(o.z-__half2float(h2)), __float2half_rn(o.w-__half2float(h3))};
        *(__half2*)(g_Gh + base)     = H0; *(__half2*)(g_Gh + base + 2) = H1;
        *(__half2*)(g_Gl + base)     = L0; *(__half2*)(g_Gl + base + 2) = L1;
    }
}

extern "C" void kernel_launch(void* const* d_in, const int* in_sizes, int n_in,
                              void* d_out, int out_size) {
    const float* H     = (const float*)d_in[0];
    const float* Wqkvz = (const float*)d_in[1];
    const float* Wba   = (const float*)d_in[2];
    const float* convw = (const float*)d_in[3];
    const float* Alog  = (const float*)d_in[4];
    const float* dtb   = (const float*)d_in[5];
    const float* nw    = (const float*)d_in[6];
    const float* Wout  = (const float*)d_in[7];
    float* out = (float*)d_out;

    float *qkvz;
    __half *Hh,*Hl,*W1,*Gh,*Gl,*W2;
    cudaGetSymbolAddress((void**)&qkvz, g_qkvz);
    cudaGetSymbolAddress((void**)&Hh, g_Hh); cudaGetSymbolAddress((void**)&Hl, g_Hl);
    cudaGetSymbolAddress((void**)&W1, g_W1);
    cudaGetSymbolAddress((void**)&Gh, g_Gh); cudaGetSymbolAddress((void**)&Gl, g_Gl);
    cudaGetSymbolAddress((void**)&W2, g_W2);

    static int smem_set = 0;
    if (!smem_set) {
        cudaFuncSetAttribute(gemm_sp, cudaFuncAttributeMaxDynamicSharedMemorySize, NSTG*STG_BYTES);
        smem_set = 1;
    }

    split_ew<<<1024, 256>>>(H, Hh, Hl, (size_t)SEQ*HID/4);
    splitT  <<<dim3(NQKVZ/32, HID/32), 256>>>(Wqkvz, W1, HID, NQKVZ);
    splitT  <<<dim3(HID/32, VALDIM/32), 256>>>(Wout, W2, VALDIM, HID);

    gemm_sp<<<dim3(SEQ/128, NQKVZ/128), 256, NSTG*STG_BYTES>>>(Hh, Hl, W1, qkvz, SEQ, NQKVZ, HID);
    gemm_ba<<<SEQ/4, 256>>>(H, Wba);
    conv_kernel<<<dim3(CONVD/128, SEQ/64), 128>>>(convw);
    prep_kernel<<<SEQ, 256>>>(Alog, dtb);
    scan_kernel<<<256, 128>>>();
    gate_kernel<<<SEQ, 256>>>(nw);

    gemm_sp<<<dim3(SEQ/128, HID/128), 256, NSTG*STG_BYTES>>>(Gh, Gl, W2, out, SEQ, HID, VALDIM);
}

// round 17
// speedup vs baseline: 1.5006x; 1.0702x over previous
#include <cuda_runtime.h>
#include <cuda_bf16.h>
#include <cuda_fp16.h>
#include <cstdint>

#define SEQ   4096
#define HID   2048
#define NQKVZ 12288
#define CONVD 8192
#define KEYDIM 2048
#define VALDIM 4096

typedef unsigned long long ull;

// ------------ scratch ------------
__device__ float g_qkvz [(size_t)SEQ * NQKVZ];
__device__ float g_ba   [SEQ * 64];
__device__ float g_mixed[(size_t)SEQ * CONVD];
__device__ float g_qn   [(size_t)SEQ * KEYDIM];
__device__ float g_kn   [(size_t)SEQ * KEYDIM];
__device__ float g_eg   [SEQ * 32];
__device__ float g_beta [SEQ * 32];
__device__ float g_core [(size_t)SEQ * VALDIM];

__device__ __half g_Hh [(size_t)SEQ * HID];
__device__ __half g_Hl [(size_t)SEQ * HID];
__device__ __half g_W1 [(size_t)NQKVZ * HID];
__device__ __half g_Gh [(size_t)SEQ * VALDIM];
__device__ __half g_Gl [(size_t)SEQ * VALDIM];
__device__ __half g_W2 [(size_t)HID * VALDIM];

// ------------ f32x2 helpers ------------
__device__ __forceinline__ ull pk2(float a, float b){ ull r; asm("mov.b64 %0,{%1,%2};":"=l"(r):"f"(a),"f"(b)); return r; }
__device__ __forceinline__ void upk2(ull v, float& a, float& b){ asm("mov.b64 {%0,%1},%2;":"=f"(a),"=f"(b):"l"(v)); }
__device__ __forceinline__ ull fma2(ull a, ull b, ull c){ ull d; asm("fma.rn.f32x2 %0,%1,%2,%3;":"=l"(d):"l"(a),"l"(b),"l"(c)); return d; }
__device__ __forceinline__ ull mul2(ull a, ull b){ ull d; asm("mul.rn.f32x2 %0,%1,%2;":"=l"(d):"l"(a),"l"(b)); return d; }
__device__ __forceinline__ ull add2(ull a, ull b){ ull d; asm("add.rn.f32x2 %0,%1,%2;":"=l"(d):"l"(a),"l"(b)); return d; }

__device__ __forceinline__ void mma_f16(float* c, const unsigned* a, const unsigned* b){
    asm volatile("mma.sync.aligned.m16n8k16.row.col.f32.f16.f16.f32 "
        "{%0,%1,%2,%3},{%4,%5,%6,%7},{%8,%9},{%0,%1,%2,%3};\n"
        : "+f"(c[0]),"+f"(c[1]),"+f"(c[2]),"+f"(c[3])
        : "r"(a[0]),"r"(a[1]),"r"(a[2]),"r"(a[3]),"r"(b[0]),"r"(b[1]));
}
__device__ __forceinline__ void cp16(uint32_t dst, const void* src){
    asm volatile("cp.async.cg.shared.global [%0], [%1], 16;" :: "r"(dst), "l"(src));
}
__device__ __forceinline__ void cp4(uint32_t dst, const void* src){
    asm volatile("cp.async.ca.shared.global [%0], [%1], 4;" :: "r"(dst), "l"(src));
}
__device__ __forceinline__ void ldsm4(unsigned* r, uint32_t a){
    asm volatile("ldmatrix.sync.aligned.m8n8.x4.shared.b16 {%0,%1,%2,%3},[%4];"
        : "=r"(r[0]),"=r"(r[1]),"=r"(r[2]),"=r"(r[3]) : "r"(a));
}
__device__ __forceinline__ void ldsm2(unsigned* r, uint32_t a){
    asm volatile("ldmatrix.sync.aligned.m8n8.x2.shared.b16 {%0,%1},[%2];"
        : "=r"(r[0]),"=r"(r[1]) : "r"(a));
}

// ------------ 3-stage pipelined split-fp16 GEMM (R13, unchanged) ------------
#define STG_BYTES 24576
#define NSTG 3
__global__ __launch_bounds__(256, 2) void gemm_sp(const __half* __restrict__ Ah,
                                                  const __half* __restrict__ Al,
                                                  const __half* __restrict__ B,
                                                  float* __restrict__ C,
                                                  int M, int N, int K) {
    extern __shared__ char smem[];
    uint32_t sbase = (uint32_t)__cvta_generic_to_shared(smem);
    const int tid = threadIdx.x;
    const int bm = blockIdx.x*128, bn = blockIdx.y*128;
    const int warp = tid >> 5, lane = tid & 31;
    const int wm = (warp >> 2)*64, wn = (warp & 3)*32;

    float acc[4][4][4];
    #pragma unroll
    for (int i=0;i<4;i++)
      #pragma unroll
      for (int j=0;j<4;j++)
        #pragma unroll
        for (int k=0;k<4;k++) acc[i][j][k]=0.f;

    auto load_stage = [&](int c){
        uint32_t so = sbase + (c % NSTG)*STG_BYTES;
        int k0 = c*32;
        #pragma unroll
        for (int i=0;i<2;i++){
            int id  = tid + i*256;
            int row = id >> 2, cc = id & 3;
            uint32_t d = row*64 + ((cc ^ ((row>>1)&3))<<4);
            size_t ga = (size_t)(bm+row)*K + k0 + cc*8;
            size_t gb = (size_t)(bn+row)*K + k0 + cc*8;
            cp16(so          + d, Ah + ga);
            cp16(so +  8192  + d, Al + ga);
            cp16(so + 16384  + d, B  + gb);
        }
        asm volatile("cp.async.commit_group;");
    };

    const int NK = K >> 5;
    load_stage(0);
    load_stage(1);

    for (int it = 0; it < NK; it++) {
        __syncthreads();
        if (it + 2 < NK) {
            load_stage(it + 2);
            asm volatile("cp.async.wait_group 2;");
        } else if (it + 1 < NK) {
            asm volatile("cp.async.wait_group 1;");
        } else {
            asm volatile("cp.async.wait_group 0;");
        }
        __syncthreads();

        uint32_t so = sbase + (it % NSTG)*STG_BYTES;
        #pragma unroll
        for (int ks=0; ks<2; ks++){
            unsigned ah[4][4], al[4][4], bf[4][2];
            #pragma unroll
            for (int mt=0; mt<4; mt++){
                int row = wm + mt*16 + (lane&15);
                int ch  = ks*2 + (lane>>4);
                uint32_t off = row*64 + ((ch ^ ((row>>1)&3))<<4);
                ldsm4(ah[mt], so + off);
                ldsm4(al[mt], so + 8192 + off);
            }
            #pragma unroll
            for (int nt=0; nt<4; nt++){
                int row = wn + nt*8 + (lane&7);
                int ch  = ks*2 + ((lane&15)>>3);
                uint32_t off = row*64 + ((ch ^ ((row>>1)&3))<<4);
                ldsm2(bf[nt], so + 16384 + off);
            }
            #pragma unroll
            for (int mt=0; mt<4; mt++)
              #pragma unroll
              for (int nt=0; nt<4; nt++){
                  mma_f16(acc[mt][nt], ah[mt], bf[nt]);
                  mma_f16(acc[mt][nt], al[mt], bf[nt]);
              }
        }
    }

    #pragma unroll
    for (int mt=0; mt<4; mt++){
        int r = bm + wm + mt*16 + (lane>>2);
        #pragma unroll
        for (int nt=0; nt<4; nt++){
            int c = bn + wn + nt*8 + (lane&3)*2;
            *(float2*)(C + (size_t) r   *N + c) = make_float2(acc[mt][nt][0], acc[mt][nt][1]);
            *(float2*)(C + (size_t)(r+8)*N + c) = make_float2(acc[mt][nt][2], acc[mt][nt][3]);
        }
    }
}

// ------------ elementwise fp32 -> fp16 hi/lo split ------------
__global__ __launch_bounds__(256) void split_ew(const float* __restrict__ in,
                                                __half* __restrict__ oh,
                                                __half* __restrict__ ol,
                                                size_t n4) {
    size_t i = (size_t)blockIdx.x*256 + threadIdx.x;
    size_t stride = (size_t)gridDim.x*256;
    for (; i < n4; i += stride) {
        float4 v = ((const float4*)in)[i];
        __half h0=__float2half_rn(v.x), h1=__float2half_rn(v.y),
               h2=__float2half_rn(v.z), h3=__float2half_rn(v.w);
        __half2 H0 = {h0,h1}, H1 = {h2,h3};
        __half2 L0 = {__float2half_rn(v.x-__half2float(h0)),
                      __float2half_rn(v.y-__half2float(h1))};
        __half2 L1 = {__float2half_rn(v.z-__half2float(h2)),
                      __float2half_rn(v.w-__half2float(h3))};
        ((__half2*)oh)[2*i]   = H0; ((__half2*)oh)[2*i+1] = H1;
        ((__half2*)ol)[2*i]   = L0; ((__half2*)ol)[2*i+1] = L1;
    }
}

// ------------ transpose + round: in[K][N] fp32 -> out[n][k] fp16 ------------
__global__ __launch_bounds__(256) void splitT(const float* __restrict__ in,
                                              __half* __restrict__ oh,
                                              int K, int N) {
    __shared__ float tile[32][33];
    int n0 = blockIdx.x*32, k0 = blockIdx.y*32;
    int tx = threadIdx.x & 31, ty = threadIdx.x >> 5;
    #pragma unroll
    for (int j = 0; j < 32; j += 8)
        tile[ty+j][tx] = in[(size_t)(k0+ty+j)*N + n0 + tx];
    __syncthreads();
    #pragma unroll
    for (int j = 0; j < 32; j += 8)
        oh[(size_t)(n0+ty+j)*K + k0 + tx] = __float2half_rn(tile[tx][ty+j]);
}

// ------------ ba = H @ W_ba ------------
__global__ __launch_bounds__(256) void gemm_ba(const float* __restrict__ A,
                                               const float* __restrict__ B) {
    int r = blockIdx.x*4 + (threadIdx.x>>6);
    int c = threadIdx.x & 63;
    const float* ar = A + (size_t)r*HID;
    float acc = 0.f;
    #pragma unroll 4
    for (int k=0;k<HID;k+=4){
        float4 a = *(const float4*)(ar+k);
        acc += a.x*B[(k  )*64+c] + a.y*B[(k+1)*64+c]
             + a.z*B[(k+2)*64+c] + a.w*B[(k+3)*64+c];
    }
    g_ba[r*64+c] = acc;
}

// ------------ causal depthwise conv(4) + silu ------------
__global__ __launch_bounds__(128) void conv_kernel(const float* __restrict__ cw) {
    int c  = blockIdx.x*128 + threadIdx.x;
    int t0 = blockIdx.y*64;
    int col;
    if (c < 2048)      col = (c>>7)*768 + (c&127);
    else if (c < 4096) { int cc=c-2048; col = (cc>>7)*768 + 128 + (cc&127); }
    else               { int cc=c-4096; col = (cc>>8)*768 + 256 + (cc&255); }
    float4 w = *(const float4*)(cw + c*4);
    float x0=0.f, x1=0.f, x2=0.f;
    if (t0 >= 3) {
        x0 = g_qkvz[(size_t)(t0-3)*NQKVZ + col];
        x1 = g_qkvz[(size_t)(t0-2)*NQKVZ + col];
        x2 = g_qkvz[(size_t)(t0-1)*NQKVZ + col];
    }
    #pragma unroll 4
    for (int t=t0; t<t0+64; t++) {
        float x3 = g_qkvz[(size_t)t*NQKVZ + col];
        float y = x0*w.x + x1*w.y + x2*w.z + x3*w.w;
        g_mixed[(size_t)t*CONVD + c] = y / (1.f + expf(-y));
        x0=x1; x1=x2; x2=x3;
    }
}

// ------------ l2norm q/k, gates ------------
__global__ __launch_bounds__(256) void prep_kernel(const float* __restrict__ Alog,
                                                   const float* __restrict__ dtb) {
    int t = blockIdx.x;
    int warp = threadIdx.x>>5, lane = threadIdx.x&31;
    #pragma unroll
    for (int i=0;i<4;i++){
        int row = warp*4+i;
        int isK = row>=16, h = row&15;
        const float* src = g_mixed + (size_t)t*CONVD + (isK?2048:0) + h*128;
        float4 v = *(const float4*)(src + lane*4);
        float ss = v.x*v.x+v.y*v.y+v.z*v.z+v.w*v.w;
        ss += __shfl_xor_sync(~0u, ss, 16);
        ss += __shfl_xor_sync(~0u, ss, 8);
        ss += __shfl_xor_sync(~0u, ss, 4);
        ss += __shfl_xor_sync(~0u, ss, 2);
        ss += __shfl_xor_sync(~0u, ss, 1);
        float sc = rsqrtf(ss + 1e-6f);
        if (!isK) sc *= 0.08838834764831845f;
        float* dst = (isK ? g_kn : g_qn) + (size_t)t*KEYDIM + h*128 + lane*4;
        *(float4*)dst = make_float4(v.x*sc, v.y*sc, v.z*sc, v.w*sc);
    }
    if (threadIdx.x < 32) {
        int h32 = threadIdx.x, h16 = h32>>1, j = h32&1;
        float b = g_ba[t*64 + h16*4 + j];
        float a = g_ba[t*64 + h16*4 + 2 + j];
        float x = a + dtb[h32];
        float sp = (x > 20.f) ? x : log1pf(expf(x));
        g_eg  [t*32 + h32] = expf(-expf(Alog[h32]) * sp);
        g_beta[t*32 + h32] = 1.f / (1.f + expf(-b));
    }
}

// ------------ gated delta-rule scan: epoch-chunked ring, 128 balanced blocks ------------
// block = (h, vb: 32 v-cols); 8 warps x 4 cols; lane = (vg=lane>>3, kg=lane&7).
// Epoch = 8 steps. Ring: 2 buffers x 8 slots. One commit group per epoch per thread.
// Slot (1280B): k 512 (chunk c at 16*(c^(c>>3))) | q 512 | v 128 | e | b
#define SE 8
#define SSLOT 1280
__global__ __launch_bounds__(256) void scan_kernel() {
    __shared__ __align__(16) char ring[2*SE*SSLOT];
    const int tid = threadIdx.x;
    const int h = blockIdx.x>>2, vb = blockIdx.x&3;
    const int warp = tid>>5, lane = tid&31;
    const int kg = lane&7, vg = lane>>3;
    const int h16 = h>>1;
    const char* kbase = (const char*)(g_kn + h16*128);
    const char* qbase = (const char*)(g_qn + h16*128);
    const char* vbase = (const char*)(g_mixed + 4096 + h*128 + vb*32);
    float* op = g_core + h*128 + vb*32 + warp*4 + vg;
    const uint32_t rb = (uint32_t)__cvta_generic_to_shared(ring);
    const int vidx = warp*4 + vg;

    auto load_epoch = [&](int e){
        uint32_t bo = rb + (e & 1)*(SE*SSLOT);
        int t0 = e*SE;
        #pragma unroll
        for (int s = 0; s < SE; s++) {
            int t = t0 + s;
            uint32_t so = bo + s*SSLOT;
            if (tid < 32) {
                cp16(so + ((tid ^ (tid>>3))<<4), kbase + (size_t)t*KEYDIM*4 + tid*16);
            } else if (tid < 64) {
                int c = tid - 32;
                cp16(so + 512 + ((c ^ (c>>3))<<4), qbase + (size_t)t*KEYDIM*4 + c*16);
            } else if (tid < 72) {
                cp16(so + 1024 + (tid-64)*16, vbase + (size_t)t*CONVD*4 + (tid-64)*16);
            } else if (tid == 72) {
                cp4(so + 1152, g_eg + (size_t)t*32 + h);
            } else if (tid == 73) {
                cp4(so + 1156, g_beta + (size_t)t*32 + h);
            }
        }
        asm volatile("cp.async.commit_group;" ::: "memory");
    };

    load_epoch(0);
    load_epoch(1);

    ull s[8];
    #pragma unroll
    for (int i=0;i<8;i++) s[i]=0ull;

    const int NE = SEQ / SE;
    for (int e = 0; e < NE; e++) {
        asm volatile("cp.async.wait_group 1;" ::: "memory");
        __syncthreads();

        const char* bo = ring + (e & 1)*(SE*SSLOT);
        #pragma unroll
        for (int st = 0; st < SE; st++) {
            const char* slot = bo + st*SSLOT;
            ull kf[8], qf[8];
            #pragma unroll
            for (int i=0;i<4;i++){
                int sw = (kg*4 + i) ^ (kg>>1);
                ulonglong2 a = *(const ulonglong2*)(slot + (sw<<4));
                ulonglong2 b = *(const ulonglong2*)(slot + 512 + (sw<<4));
                kf[2*i]=a.x; kf[2*i+1]=a.y;
                qf[2*i]=b.x; qf[2*i+1]=b.y;
            }
            float vv = ((const float*)(slot + 1024))[vidx];
            float ee = *(const float*)(slot + 1152);
            float bt = *(const float*)(slot + 1156);

            ull pa0 = fma2(s[1],kf[1], mul2(s[0],kf[0]));
            ull pa1 = fma2(s[3],kf[3], mul2(s[2],kf[2]));
            ull pa2 = fma2(s[5],kf[5], mul2(s[4],kf[4]));
            ull pa3 = fma2(s[7],kf[7], mul2(s[6],kf[6]));
            ull pb0 = fma2(s[1],qf[1], mul2(s[0],qf[0]));
            ull pb1 = fma2(s[3],qf[3], mul2(s[2],qf[2]));
            ull pb2 = fma2(s[5],qf[5], mul2(s[4],qf[4]));
            ull pb3 = fma2(s[7],qf[7], mul2(s[6],qf[6]));
            ull pc0 = fma2(kf[1],qf[1], mul2(kf[0],qf[0]));
            ull pc1 = fma2(kf[3],qf[3], mul2(kf[2],qf[2]));
            ull pc2 = fma2(kf[5],qf[5], mul2(kf[4],qf[4]));
            ull pc3 = fma2(kf[7],qf[7], mul2(kf[6],qf[6]));
            pa0 = add2(add2(pa0,pa1), add2(pa2,pa3));
            pb0 = add2(add2(pb0,pb1), add2(pb2,pb3));
            pc0 = add2(add2(pc0,pc1), add2(pc2,pc3));
            float ax, ay, bx, by, cx, cy;
            upk2(pa0, ax, ay); upk2(pb0, bx, by); upk2(pc0, cx, cy);
            float rk = ax + ay, rq = bx + by, rkq = cx + cy;
            #pragma unroll
            for (int m = 1; m <= 4; m <<= 1) {
                rk  += __shfl_xor_sync(~0u, rk,  m);
                rq  += __shfl_xor_sync(~0u, rq,  m);
                rkq += __shfl_xor_sync(~0u, rkq, m);
            }
            float delta = (vv - ee*rk) * bt;
            float o = ee*rq + rkq*delta;
            ull e2 = pk2(ee, ee), d2 = pk2(delta, delta);
            #pragma unroll
            for (int i=0;i<8;i++) s[i] = fma2(s[i], e2, mul2(kf[i], d2));
            if (kg == 0) op[(size_t)(e*SE + st)*VALDIM] = o;
        }

        __syncthreads();
        if (e + 2 < NE) load_epoch(e + 2);
        else asm volatile("cp.async.commit_group;" ::: "memory");
    }
}

// ------------ RMS norm + silu(z) gate (fused fp16 split output) ------------
__global__ __launch_bounds__(256) void gate_kernel(const float* __restrict__ nw) {
    int t = blockIdx.x;
    int warp = threadIdx.x>>5, lane = threadIdx.x&31;
    #pragma unroll
    for (int i=0;i<4;i++){
        int h = warp*4 + i;
        const float* cp = g_core + (size_t)t*VALDIM + h*128;
        float4 c = *(const float4*)(cp + lane*4);
        float ss = c.x*c.x + c.y*c.y + c.z*c.z + c.w*c.w;
        ss += __shfl_xor_sync(~0u, ss, 16);
        ss += __shfl_xor_sync(~0u, ss, 8);
        ss += __shfl_xor_sync(~0u, ss, 4);
        ss += __shfl_xor_sync(~0u, ss, 2);
        ss += __shfl_xor_sync(~0u, ss, 1);
        float sc = rsqrtf(ss*(1.f/128.f) + 1e-6f);
        const float* zp = g_qkvz + (size_t)t*NQKVZ + (h>>1)*768 + 512 + (h&1)*128;
        float4 z = *(const float4*)(zp + lane*4);
        float4 w = *(const float4*)(nw + lane*4);
        float4 o;
        o.x = c.x*sc*w.x * (z.x/(1.f+expf(-z.x)));
        o.y = c.y*sc*w.y * (z.y/(1.f+expf(-z.y)));
        o.z = c.z*sc*w.z * (z.z/(1.f+expf(-z.z)));
        o.w = c.w*sc*w.w * (z.w/(1.f+expf(-z.w)));
        size_t base = (size_t)t*VALDIM + h*128 + lane*4;
        __half h0=__float2half_rn(o.x), h1=__float2half_rn(o.y),
               h2=__float2half_rn(o.z), h3=__float2half_rn(o.w);
        __half2 H0={h0,h1}, H1={h2,h3};
        __half2 L0={__float2half_rn(o.x-__half2float(h0)), __float2half_rn(o.y-__half2float(h1))};
        __half2 L1={__float2half_rn(o.z-__half2float(h2)), __float2half_rn(o.w-__half2float(h3))};
        *(__half2*)(g_Gh + base)     = H0; *(__half2*)(g_Gh + base + 2) = H1;
        *(__half2*)(g_Gl + base)     = L0; *(__half2*)(g_Gl + base + 2) = L1;
    }
}

extern "C" void kernel_launch(void* const* d_in, const int* in_sizes, int n_in,
                              void* d_out, int out_size) {
    const float* H     = (const float*)d_in[0];
    const float* Wqkvz = (const float*)d_in[1];
    const float* Wba   = (const float*)d_in[2];
    const float* convw = (const float*)d_in[3];
    const float* Alog  = (const float*)d_in[4];
    const float* dtb   = (const float*)d_in[5];
    const float* nw    = (const float*)d_in[6];
    const float* Wout  = (const float*)d_in[7];
    float* out = (float*)d_out;

    float *qkvz;
    __half *Hh,*Hl,*W1,*Gh,*Gl,*W2;
    cudaGetSymbolAddress((void**)&qkvz, g_qkvz);
    cudaGetSymbolAddress((void**)&Hh, g_Hh); cudaGetSymbolAddress((void**)&Hl, g_Hl);
    cudaGetSymbolAddress((void**)&W1, g_W1);
    cudaGetSymbolAddress((void**)&Gh, g_Gh); cudaGetSymbolAddress((void**)&Gl, g_Gl);
    cudaGetSymbolAddress((void**)&W2, g_W2);

    static int smem_set = 0;
    if (!smem_set) {
        cudaFuncSetAttribute(gemm_sp, cudaFuncAttributeMaxDynamicSharedMemorySize, NSTG*STG_BYTES);
        smem_set = 1;
    }

    split_ew<<<1024, 256>>>(H, Hh, Hl, (size_t)SEQ*HID/4);
    splitT  <<<dim3(NQKVZ/32, HID/32), 256>>>(Wqkvz, W1, HID, NQKVZ);
    splitT  <<<dim3(HID/32, VALDIM/32), 256>>>(Wout, W2, VALDIM, HID);

    gemm_sp<<<dim3(SEQ/128, NQKVZ/128), 256, NSTG*STG_BYTES>>>(Hh, Hl, W1, qkvz, SEQ, NQKVZ, HID);
    gemm_ba<<<SEQ/4, 256>>>(H, Wba);
    conv_kernel<<<dim3(CONVD/128, SEQ/64), 128>>>(convw);
    prep_kernel<<<SEQ, 256>>>(Alog, dtb);
    scan_kernel<<<128, 256>>>();
    gate_kernel<<<SEQ, 256>>>(nw);

    gemm_sp<<<dim3(SEQ/128, HID/128), 256, NSTG*STG_BYTES>>>(Gh, Gl, W2, out, SEQ, HID, VALDIM);
}